// round 9
// baseline (speedup 1.0000x reference)
#include <cuda_runtime.h>
#include <cuda_fp16.h>

#define T_STEPS 200
#define NIN     5
#define H       32
#define G4      128
#define NB      16            // batches per warp-pair group
#define PAIRS   4             // warp pairs per CTA
#define THREADS 256

#define WPITCH  56                         // halfs per W row
#define WBYTES  (G4 * WPITCH * 2)          // 14336
#define OFF_H   WBYTES
#define HPITCH  48                         // bytes per Hbuf row
#define HGROUPSZ (48 * HPITCH)             // 2304 per group
#define OFF_EXCH (OFF_H + PAIRS * HGROUPSZ)   // 23552
#define EXCH_PAIR 2048
#define SMEM_TOTAL (OFF_EXCH + PAIRS * EXCH_PAIR)  // 31744

// ---------- PTX helpers ----------
__device__ __forceinline__ unsigned smem_u32(const void* p) {
    unsigned a;
    asm("{ .reg .u64 t; cvta.to.shared.u64 t, %1; cvt.u32.u64 %0, t; }"
        : "=r"(a) : "l"(p));
    return a;
}
__device__ __forceinline__ void ldsm_x4(unsigned& a0, unsigned& a1,
                                        unsigned& a2, unsigned& a3, unsigned addr) {
    asm volatile("ldmatrix.sync.aligned.m8n8.x4.shared.b16 {%0,%1,%2,%3}, [%4];"
                 : "=r"(a0), "=r"(a1), "=r"(a2), "=r"(a3) : "r"(addr));
}
__device__ __forceinline__ void ldsm_x4t(unsigned& b0, unsigned& b1,
                                         unsigned& b2, unsigned& b3, unsigned addr) {
    asm volatile("ldmatrix.sync.aligned.m8n8.x4.trans.shared.b16 {%0,%1,%2,%3}, [%4];"
                 : "=r"(b0), "=r"(b1), "=r"(b2), "=r"(b3) : "r"(addr));
}
#define MMA(Cr, A0, A1, A2, A3, B0, B1)                                        \
    asm volatile("mma.sync.aligned.m16n8k16.row.col.f32.f16.f16.f32 "          \
                 "{%0,%1,%2,%3}, {%4,%5,%6,%7}, {%8,%9}, {%0,%1,%2,%3};"       \
                 : "+f"((Cr)[0]), "+f"((Cr)[1]), "+f"((Cr)[2]), "+f"((Cr)[3])  \
                 : "r"(A0), "r"(A1), "r"(A2), "r"(A3), "r"(B0), "r"(B1))

__device__ __forceinline__ void sts32(unsigned addr, unsigned v) {
    asm volatile("st.shared.b32 [%0], %1;" :: "r"(addr), "r"(v) : "memory");
}
__device__ __forceinline__ void sts16(unsigned addr, unsigned short v) {
    asm volatile("st.shared.b16 [%0], %1;" :: "r"(addr), "h"(v) : "memory");
}
__device__ __forceinline__ unsigned lds32(unsigned addr) {
    unsigned v;
    asm volatile("ld.shared.b32 %0, [%1];" : "=r"(v) : "r"(addr) : "memory");
    return v;
}
#define BARP(id) asm volatile("bar.sync %0, 64;" :: "r"(id) : "memory")

// ---------- packed f16x2 helpers ----------
__device__ __forceinline__ __half2 tanh2(__half2 v) {
    unsigned u = *reinterpret_cast<unsigned*>(&v), r;
    asm("tanh.approx.f16x2 %0, %1;" : "=r"(r) : "r"(u));
    return *reinterpret_cast<__half2*>(&r);
}
__device__ __forceinline__ __half2 pack2h(float e0, float e1) {   // low=e0
    unsigned r;
    asm("cvt.rn.f16x2.f32 %0, %1, %2;" : "=r"(r) : "f"(e1), "f"(e0));
    return *reinterpret_cast<__half2*>(&r);
}
__device__ __forceinline__ unsigned h2bits(__half2 v) {
    return *reinterpret_cast<unsigned*>(&v);
}
__device__ __forceinline__ __half2 bits2h(unsigned u) {
    return *reinterpret_cast<__half2*>(&u);
}

__global__ void __launch_bounds__(THREADS, 2)
lstm_pair_kernel(const float* __restrict__ x,
                 const float* __restrict__ W_ih,
                 const float* __restrict__ W_hh,
                 const float* __restrict__ b_ih,
                 const float* __restrict__ b_hh,
                 const float* __restrict__ W_fc,
                 const float* __restrict__ b_fc,
                 float* __restrict__ out, int B) {
    __shared__ __align__(16) char smraw[SMEM_TOTAL];
    const unsigned sbase = smem_u32(smraw);

    const int tid  = threadIdx.x;
    const int wid  = tid >> 5;
    const int lane = tid & 31;
    const int pair = wid >> 1;          // 0..3
    const int par  = wid & 1;           // 0 = gates i,f ; 1 = gates g,o
    const int gl   = lane >> 2;
    const int tl   = lane & 3;

    __half* Wsm = (__half*)smraw;

    // ============ init: W fp16 (x_lo duplicated cols) ============
    if (tid < G4) {
        const int g = tid;
        for (int k = 0; k < WPITCH; ++k) {
            float v;
            if (k < H)            v = W_hh[g * H + k];
            else if (k < 37)      v = W_ih[g * NIN + (k - 32)];
            else if (k == 37)     v = b_ih[g] + b_hh[g];
            else if (k >= 38 && k < 43) v = W_ih[g * NIN + (k - 38)];
            else                  v = 0.0f;
            Wsm[g * WPITCH + k] = __float2half(v);
        }
    }
    {   // zero Hbuf region
        unsigned* hz = (unsigned*)(smraw + OFF_H);
        for (int i = tid; i < PAIRS * HGROUPSZ / 4; i += THREADS) hz[i] = 0u;
    }
    __syncthreads();
    if (tid < PAIRS * NB) {  // ones row k=37 per group
        int pp = tid / NB, b = tid % NB;
        *(__half*)(smraw + OFF_H + pp * HGROUPSZ + 37 * HPITCH + b * 2) =
            __float2half(1.0f);
    }

    const int wb0 = blockIdx.x * (PAIRS * NB) + pair * NB;

    const unsigned laneA = (unsigned)((lane & 15) * (WPITCH * 2) + (lane >> 4) * 16);
    const unsigned hgroup = sbase + OFF_H + pair * HGROUPSZ;
    const unsigned addrB  = hgroup + (unsigned)((lane & 15) * HPITCH + (lane >> 4) * 16);
    const unsigned epair  = sbase + OFF_EXCH + pair * EXCH_PAIR;
    const unsigned wrb = epair + (par ? 0u : 1024u);   // even writes dir1, odd dir0
    const unsigned rdb = epair + (par ? 1024u : 0u);
    const unsigned exoff = (unsigned)(gl * 32 + 2 * tl * 2);  // + rr*256 + nt*16

    // ---- pin this warp's 4 W m-tiles (48 regs) ----
    unsigned wa[4][3][4];
#pragma unroll
    for (int mtL = 0; mtL < 4; ++mtL)
#pragma unroll
        for (int kc = 0; kc < 3; ++kc)
            ldsm_x4(wa[mtL][kc][0], wa[mtL][kc][1], wa[mtL][kc][2], wa[mtL][kc][3],
                    sbase + laneA +
                    (unsigned)((par * 4 + mtL) * (16 * WPITCH * 2) + kc * 32));

    const float* xr = x + (size_t)(wb0 + lane) * (T_STEPS * NIN);  // lane<16 valid
    float xv[NIN];

    // stage x(0)
    if (par == 0 && lane < NB) {
#pragma unroll
        for (int d = 0; d < NIN; ++d) {
            float v = xr[d];
            __half xh = __float2half(v);
            __half xl = __float2half(v - __half2float(xh));
            sts16(hgroup + (unsigned)((32 + d) * HPITCH + lane * 2),
                  *reinterpret_cast<unsigned short*>(&xh));
            sts16(hgroup + (unsigned)((38 + d) * HPITCH + lane * 2),
                  *reinterpret_cast<unsigned short*>(&xl));
        }
    }
    __syncthreads();

    float creg[8];
    __half2 h2loc[4];
#pragma unroll
    for (int i = 0; i < 8; ++i) creg[i] = 0.0f;
#pragma unroll
    for (int i = 0; i < 4; ++i) h2loc[i] = bits2h(0u);

    const __half2 h05 = __float2half2_rn(0.5f);
    const int barid = pair + 1;

#pragma unroll 1
    for (int t = 0; t < T_STEPS; ++t) {
        // ---- MMA: this warp's 4 m-tiles x 2 n-tiles x 3 k ----
        float Cacc[4][2][4];
#pragma unroll
        for (int m = 0; m < 4; ++m)
#pragma unroll
            for (int n = 0; n < 2; ++n)
#pragma unroll
                for (int e = 0; e < 4; ++e) Cacc[m][n][e] = 0.0f;

#pragma unroll
        for (int kc = 0; kc < 3; ++kc) {
            unsigned rb0, rb1, rb2, rb3;
            ldsm_x4t(rb0, rb1, rb2, rb3, addrB + (unsigned)(kc * 16 * HPITCH));
#pragma unroll
            for (int mtL = 0; mtL < 4; ++mtL) {
                MMA(Cacc[mtL][0], wa[mtL][kc][0], wa[mtL][kc][1],
                    wa[mtL][kc][2], wa[mtL][kc][3], rb0, rb1);
                MMA(Cacc[mtL][1], wa[mtL][kc][0], wa[mtL][kc][1],
                    wa[mtL][kc][2], wa[mtL][kc][3], rb2, rb3);
            }
        }

        // ---- prefetch next x ----
        if (par == 0 && lane < NB && t + 1 < T_STEPS) {
#pragma unroll
            for (int d = 0; d < NIN; ++d) xv[d] = xr[(t + 1) * NIN + d];
        }

        // ---- activations: write complement halves, keep own ----
        __half2 own0[2][2], own1[2][2];
        if (par == 0) {
            // write sig(i),sig(f) for u16-31 (mtL 1,3); keep u0-15 (mtL 0,2)
#pragma unroll
            for (int nt = 0; nt < 2; ++nt)
#pragma unroll
                for (int rr = 0; rr < 2; ++rr) {
                    unsigned o = exoff + (unsigned)(rr * 256 + nt * 16);
                    __half2 si = __hfma2(tanh2(__hmul2(
                        pack2h(Cacc[1][nt][rr*2], Cacc[1][nt][rr*2+1]), h05)), h05, h05);
                    sts32(wrb + o, h2bits(si));
                    __half2 sf = __hfma2(tanh2(__hmul2(
                        pack2h(Cacc[3][nt][rr*2], Cacc[3][nt][rr*2+1]), h05)), h05, h05);
                    sts32(wrb + 512u + o, h2bits(sf));
                    own0[nt][rr] = __hfma2(tanh2(__hmul2(
                        pack2h(Cacc[0][nt][rr*2], Cacc[0][nt][rr*2+1]), h05)), h05, h05);
                    own1[nt][rr] = __hfma2(tanh2(__hmul2(
                        pack2h(Cacc[2][nt][rr*2], Cacc[2][nt][rr*2+1]), h05)), h05, h05);
                }
        } else {
            // write tanh(g),sig(o) for u0-15 (mtL 0,2); keep u16-31 (mtL 1,3)
#pragma unroll
            for (int nt = 0; nt < 2; ++nt)
#pragma unroll
                for (int rr = 0; rr < 2; ++rr) {
                    unsigned o = exoff + (unsigned)(rr * 256 + nt * 16);
                    __half2 tg = tanh2(
                        pack2h(Cacc[0][nt][rr*2], Cacc[0][nt][rr*2+1]));
                    sts32(wrb + o, h2bits(tg));
                    __half2 so = __hfma2(tanh2(__hmul2(
                        pack2h(Cacc[2][nt][rr*2], Cacc[2][nt][rr*2+1]), h05)), h05, h05);
                    sts32(wrb + 512u + o, h2bits(so));
                    own0[nt][rr] = tanh2(
                        pack2h(Cacc[1][nt][rr*2], Cacc[1][nt][rr*2+1]));
                    own1[nt][rr] = __hfma2(tanh2(__hmul2(
                        pack2h(Cacc[3][nt][rr*2], Cacc[3][nt][rr*2+1]), h05)), h05, h05);
                }
        }
        BARP(barid);

        // ---- read complements, update c/h for own 16 units ----
#pragma unroll
        for (int nt = 0; nt < 2; ++nt)
#pragma unroll
            for (int rr = 0; rr < 2; ++rr) {
                unsigned o = exoff + (unsigned)(rr * 256 + nt * 16);
                __half2 r0 = bits2h(lds32(rdb + o));
                __half2 r1 = bits2h(lds32(rdb + 512u + o));
                __half2 gi = (par == 0) ? own0[nt][rr] : r0;
                __half2 gf = (par == 0) ? own1[nt][rr] : r1;
                __half2 gg = (par == 0) ? r0 : own0[nt][rr];
                __half2 go = (par == 0) ? r1 : own1[nt][rr];
                __half2 ig = __hmul2(gi, gg);
                const int idx = (nt * 2 + rr) * 2;
                float c0 = fmaf(__low2float(gf),  creg[idx],     __low2float(ig));
                float c1 = fmaf(__high2float(gf), creg[idx + 1], __high2float(ig));
                creg[idx] = c0;
                creg[idx + 1] = c1;
                __half2 hv = __hmul2(go, tanh2(pack2h(c0, c1)));
                h2loc[nt * 2 + rr] = hv;
                sts32(hgroup + (unsigned)((par * 16 + rr * 8 + gl) * HPITCH
                                          + (nt * 8 + 2 * tl) * 2),
                      h2bits(hv));
            }

        // ---- stage x(t+1) ----
        if (par == 0 && lane < NB) {
#pragma unroll
            for (int d = 0; d < NIN; ++d) {
                __half xh = __float2half(xv[d]);
                __half xl = __float2half(xv[d] - __half2float(xh));
                sts16(hgroup + (unsigned)((32 + d) * HPITCH + lane * 2),
                      *reinterpret_cast<unsigned short*>(&xh));
                sts16(hgroup + (unsigned)((38 + d) * HPITCH + lane * 2),
                      *reinterpret_cast<unsigned short*>(&xl));
            }
        }
        BARP(barid);
    }

    // ============ final projection ============
    float acc[2][2][2];   // [nt][e][o]
#pragma unroll
    for (int nt = 0; nt < 2; ++nt)
#pragma unroll
        for (int e = 0; e < 2; ++e) { acc[nt][e][0] = 0.0f; acc[nt][e][1] = 0.0f; }
#pragma unroll
    for (int rr = 0; rr < 2; ++rr) {
        const int u = par * 16 + rr * 8 + gl;
        const float w0 = W_fc[u], w1 = W_fc[H + u];
#pragma unroll
        for (int nt = 0; nt < 2; ++nt) {
            const __half2 hv = h2loc[nt * 2 + rr];
            const float h0 = __low2float(hv), h1 = __high2float(hv);
            acc[nt][0][0] = fmaf(h0, w0, acc[nt][0][0]);
            acc[nt][0][1] = fmaf(h0, w1, acc[nt][0][1]);
            acc[nt][1][0] = fmaf(h1, w0, acc[nt][1][0]);
            acc[nt][1][1] = fmaf(h1, w1, acc[nt][1][1]);
        }
    }
#pragma unroll
    for (int off = 4; off <= 16; off <<= 1)
#pragma unroll
        for (int nt = 0; nt < 2; ++nt)
#pragma unroll
            for (int e = 0; e < 2; ++e) {
                acc[nt][e][0] += __shfl_xor_sync(0xffffffffu, acc[nt][e][0], off);
                acc[nt][e][1] += __shfl_xor_sync(0xffffffffu, acc[nt][e][1], off);
            }
    float* scratch = (float*)(smraw + OFF_EXCH + pair * EXCH_PAIR);
    if (par == 1 && lane < 4) {
#pragma unroll
        for (int nt = 0; nt < 2; ++nt)
#pragma unroll
            for (int e = 0; e < 2; ++e) {
                const int col = nt * 8 + 2 * lane + e;
                scratch[col * 2 + 0] = acc[nt][e][0];
                scratch[col * 2 + 1] = acc[nt][e][1];
            }
    }
    BARP(barid);
    if (par == 0 && lane < 4) {
        const float f0 = b_fc[0], f1 = b_fc[1];
#pragma unroll
        for (int nt = 0; nt < 2; ++nt)
#pragma unroll
            for (int e = 0; e < 2; ++e) {
                const int col = nt * 8 + 2 * lane + e;
                out[(wb0 + col) * 2 + 0] = acc[nt][e][0] + scratch[col * 2 + 0] + f0;
                out[(wb0 + col) * 2 + 1] = acc[nt][e][1] + scratch[col * 2 + 1] + f1;
            }
    }
}

extern "C" void kernel_launch(void* const* d_in, const int* in_sizes, int n_in,
                              void* d_out, int out_size) {
    const float* x    = (const float*)d_in[0];
    const float* W_ih = (const float*)d_in[1];
    const float* W_hh = (const float*)d_in[2];
    const float* b_ih = (const float*)d_in[3];
    const float* b_hh = (const float*)d_in[4];
    const float* W_fc = (const float*)d_in[5];
    const float* b_fc = (const float*)d_in[6];
    float* out = (float*)d_out;

    int B = in_sizes[0] / (T_STEPS * NIN);
    int bpc = PAIRS * NB;                      // 64 batches per CTA
    int blocks = (B + bpc - 1) / bpc;
    lstm_pair_kernel<<<blocks, THREADS>>>(x, W_ih, W_hh, b_ih, b_hh,
                                          W_fc, b_fc, out, B);
}

// round 10
// speedup vs baseline: 1.0971x; 1.0971x over previous
#include <cuda_runtime.h>
#include <cuda_fp16.h>

#define T_STEPS 200
#define NIN     5
#define H       32
#define G4      128
#define NB      16            // batches per warp-pair group
#define PAIRS   4             // warp pairs per CTA
#define THREADS 256

#define WPITCH  56                         // halfs per W row
#define WBYTES  (G4 * WPITCH * 2)          // 14336
#define OFF_H   WBYTES
#define HPITCH  48                         // bytes per Hbuf row
#define HBUFSZ  (48 * HPITCH)              // 2304 per buffer
#define OFF_SCR (OFF_H + PAIRS * 2 * HBUFSZ)   // 32768
#define SMEM_TOTAL (OFF_SCR + PAIRS * 256)     // 33792

// ---------- PTX helpers ----------
__device__ __forceinline__ unsigned smem_u32(const void* p) {
    unsigned a;
    asm("{ .reg .u64 t; cvta.to.shared.u64 t, %1; cvt.u32.u64 %0, t; }"
        : "=r"(a) : "l"(p));
    return a;
}
__device__ __forceinline__ void ldsm_x4(unsigned& a0, unsigned& a1,
                                        unsigned& a2, unsigned& a3, unsigned addr) {
    asm volatile("ldmatrix.sync.aligned.m8n8.x4.shared.b16 {%0,%1,%2,%3}, [%4];"
                 : "=r"(a0), "=r"(a1), "=r"(a2), "=r"(a3) : "r"(addr));
}
__device__ __forceinline__ void ldsm_x4t(unsigned& b0, unsigned& b1,
                                         unsigned& b2, unsigned& b3, unsigned addr) {
    asm volatile("ldmatrix.sync.aligned.m8n8.x4.trans.shared.b16 {%0,%1,%2,%3}, [%4];"
                 : "=r"(b0), "=r"(b1), "=r"(b2), "=r"(b3) : "r"(addr));
}
#define MMA(Cr, A0, A1, A2, A3, B0, B1)                                        \
    asm volatile("mma.sync.aligned.m16n8k16.row.col.f32.f16.f16.f32 "          \
                 "{%0,%1,%2,%3}, {%4,%5,%6,%7}, {%8,%9}, {%0,%1,%2,%3};"       \
                 : "+f"((Cr)[0]), "+f"((Cr)[1]), "+f"((Cr)[2]), "+f"((Cr)[3])  \
                 : "r"(A0), "r"(A1), "r"(A2), "r"(A3), "r"(B0), "r"(B1))

__device__ __forceinline__ void sts32(unsigned addr, unsigned v) {
    asm volatile("st.shared.b32 [%0], %1;" :: "r"(addr), "r"(v) : "memory");
}
__device__ __forceinline__ void sts16(unsigned addr, unsigned short v) {
    asm volatile("st.shared.b16 [%0], %1;" :: "r"(addr), "h"(v) : "memory");
}
#define BARP(id) asm volatile("bar.sync %0, 64;" :: "r"(id) : "memory")

// ---------- packed f16x2 helpers ----------
__device__ __forceinline__ __half2 tanh2(__half2 v) {
    unsigned u = *reinterpret_cast<unsigned*>(&v), r;
    asm("tanh.approx.f16x2 %0, %1;" : "=r"(r) : "r"(u));
    return *reinterpret_cast<__half2*>(&r);
}
__device__ __forceinline__ __half2 pack2h(float e0, float e1) {   // low=e0
    unsigned r;
    asm("cvt.rn.f16x2.f32 %0, %1, %2;" : "=r"(r) : "f"(e1), "f"(e0));
    return *reinterpret_cast<__half2*>(&r);
}
__device__ __forceinline__ unsigned h2bits(__half2 v) {
    return *reinterpret_cast<unsigned*>(&v);
}
__device__ __forceinline__ __half2 bits2h(unsigned u) {
    return *reinterpret_cast<__half2*>(&u);
}

__global__ void __launch_bounds__(THREADS, 2)
lstm_msplit_kernel(const float* __restrict__ x,
                   const float* __restrict__ W_ih,
                   const float* __restrict__ W_hh,
                   const float* __restrict__ b_ih,
                   const float* __restrict__ b_hh,
                   const float* __restrict__ W_fc,
                   const float* __restrict__ b_fc,
                   float* __restrict__ out, int B) {
    __shared__ __align__(16) char smraw[SMEM_TOTAL];
    const unsigned sbase = smem_u32(smraw);

    const int tid  = threadIdx.x;
    const int wid  = tid >> 5;
    const int lane = tid & 31;
    const int pair = wid >> 1;          // 0..3
    const int par  = wid & 1;           // owns units 16*par .. 16*par+15
    const int gl   = lane >> 2;
    const int tl   = lane & 3;

    __half* Wsm = (__half*)smraw;

    // ============ init: W fp16 (x_lo duplicated cols) ============
    if (tid < G4) {
        const int g = tid;
        for (int k = 0; k < WPITCH; ++k) {
            float v;
            if (k < H)            v = W_hh[g * H + k];
            else if (k < 37)      v = W_ih[g * NIN + (k - 32)];
            else if (k == 37)     v = b_ih[g] + b_hh[g];
            else if (k >= 38 && k < 43) v = W_ih[g * NIN + (k - 38)];
            else                  v = 0.0f;
            Wsm[g * WPITCH + k] = __float2half(v);
        }
    }
    {   // zero both Hbuf buffers for all pairs
        unsigned* hz = (unsigned*)(smraw + OFF_H);
        for (int i = tid; i < PAIRS * 2 * HBUFSZ / 4; i += THREADS) hz[i] = 0u;
    }
    __syncthreads();
    if (tid < PAIRS * 2 * NB) {  // ones row k=37 in both buffers
        int pp = tid / (2 * NB), rem = tid % (2 * NB);
        int bf = rem / NB, b = rem % NB;
        *(__half*)(smraw + OFF_H + (pp * 2 + bf) * HBUFSZ + 37 * HPITCH + b * 2) =
            __float2half(1.0f);
    }

    const int wb0 = blockIdx.x * (PAIRS * NB) + pair * NB;

    const unsigned laneA = (unsigned)((lane & 15) * (WPITCH * 2) + (lane >> 4) * 16);
    const unsigned hb0   = sbase + OFF_H + pair * 2 * HBUFSZ;
    const unsigned bOff  = (unsigned)((lane & 15) * HPITCH + (lane >> 4) * 16);

    // ---- pin this warp's 4 W m-tiles: gates i,f,g,o for its 16 units ----
    unsigned wa[4][3][4];
#pragma unroll
    for (int g = 0; g < 4; ++g)
#pragma unroll
        for (int kc = 0; kc < 3; ++kc)
            ldsm_x4(wa[g][kc][0], wa[g][kc][1], wa[g][kc][2], wa[g][kc][3],
                    sbase + laneA +
                    (unsigned)((par + 2 * g) * (16 * WPITCH * 2) + kc * 32));

    const float* xr = x + (size_t)(wb0 + lane) * (T_STEPS * NIN);  // lane<16 valid
    float xv[NIN];

    // stage x(0) into buffer 0
    if (par == 0 && lane < NB) {
#pragma unroll
        for (int d = 0; d < NIN; ++d) {
            float v = xr[d];
            __half xh = __float2half(v);
            __half xl = __float2half(v - __half2float(xh));
            sts16(hb0 + (unsigned)((32 + d) * HPITCH + lane * 2),
                  *reinterpret_cast<unsigned short*>(&xh));
            sts16(hb0 + (unsigned)((38 + d) * HPITCH + lane * 2),
                  *reinterpret_cast<unsigned short*>(&xl));
        }
    }
    __syncthreads();

    float creg[8];
    __half2 h2loc[4];
#pragma unroll
    for (int i = 0; i < 8; ++i) creg[i] = 0.0f;
#pragma unroll
    for (int i = 0; i < 4; ++i) h2loc[i] = bits2h(0u);

    const __half2 h05 = __float2half2_rn(0.5f);
    const int barid = pair + 1;
    unsigned cur = 0;

#pragma unroll 1
    for (int t = 0; t < T_STEPS; ++t) {
        const unsigned curb = hb0 + cur * HBUFSZ;
        const unsigned nxtb = hb0 + (cur ^ 1u) * HBUFSZ;

        // ---- MMA: 4 gate-tiles x 2 n-tiles x 3 k (B from current buffer) ----
        float Cacc[4][2][4];
#pragma unroll
        for (int m = 0; m < 4; ++m)
#pragma unroll
            for (int n = 0; n < 2; ++n)
#pragma unroll
                for (int e = 0; e < 4; ++e) Cacc[m][n][e] = 0.0f;

#pragma unroll
        for (int kc = 0; kc < 3; ++kc) {
            unsigned rb0, rb1, rb2, rb3;
            ldsm_x4t(rb0, rb1, rb2, rb3, curb + bOff + (unsigned)(kc * 16 * HPITCH));
#pragma unroll
            for (int g = 0; g < 4; ++g) {
                MMA(Cacc[g][0], wa[g][kc][0], wa[g][kc][1],
                    wa[g][kc][2], wa[g][kc][3], rb0, rb1);
                MMA(Cacc[g][1], wa[g][kc][0], wa[g][kc][1],
                    wa[g][kc][2], wa[g][kc][3], rb2, rb3);
            }
        }

        // ---- prefetch next x ----
        const bool havex = (par == 0) && (lane < NB) && (t + 1 < T_STEPS);
        if (havex) {
#pragma unroll
            for (int d = 0; d < NIN; ++d) xv[d] = xr[(t + 1) * NIN + d];
        }

        // ---- warp-local cell update (no exchange) ----
#pragma unroll
        for (int nt = 0; nt < 2; ++nt)
#pragma unroll
            for (int rr = 0; rr < 2; ++rr) {
                const int j0 = rr * 2, j1 = rr * 2 + 1;
                __half2 gi = __hfma2(tanh2(__hmul2(
                    pack2h(Cacc[0][nt][j0], Cacc[0][nt][j1]), h05)), h05, h05);
                __half2 gf = __hfma2(tanh2(__hmul2(
                    pack2h(Cacc[1][nt][j0], Cacc[1][nt][j1]), h05)), h05, h05);
                __half2 gg = tanh2(pack2h(Cacc[2][nt][j0], Cacc[2][nt][j1]));
                __half2 go = __hfma2(tanh2(__hmul2(
                    pack2h(Cacc[3][nt][j0], Cacc[3][nt][j1]), h05)), h05, h05);
                __half2 ig = __hmul2(gi, gg);
                const int idx = (nt * 2 + rr) * 2;
                float c0 = fmaf(__low2float(gf),  creg[idx],     __low2float(ig));
                float c1 = fmaf(__high2float(gf), creg[idx + 1], __high2float(ig));
                creg[idx] = c0;
                creg[idx + 1] = c1;
                __half2 hv = __hmul2(go, tanh2(pack2h(c0, c1)));
                h2loc[nt * 2 + rr] = hv;
                sts32(nxtb + (unsigned)((par * 16 + rr * 8 + gl) * HPITCH
                                        + (nt * 8 + 2 * tl) * 2),
                      h2bits(hv));
            }

        // ---- stage x(t+1) into next buffer ----
        if (havex) {
#pragma unroll
            for (int d = 0; d < NIN; ++d) {
                __half xh = __float2half(xv[d]);
                __half xl = __float2half(xv[d] - __half2float(xh));
                sts16(nxtb + (unsigned)((32 + d) * HPITCH + lane * 2),
                      *reinterpret_cast<unsigned short*>(&xh));
                sts16(nxtb + (unsigned)((38 + d) * HPITCH + lane * 2),
                      *reinterpret_cast<unsigned short*>(&xl));
            }
        }
        BARP(barid);   // partner's h-half visible before next step's LDSM
        cur ^= 1u;
    }

    // ============ final projection (each warp: its 16 units) ============
    float acc[2][2][2];   // [nt][e][o]
#pragma unroll
    for (int nt = 0; nt < 2; ++nt)
#pragma unroll
        for (int e = 0; e < 2; ++e) { acc[nt][e][0] = 0.0f; acc[nt][e][1] = 0.0f; }
#pragma unroll
    for (int rr = 0; rr < 2; ++rr) {
        const int u = par * 16 + rr * 8 + gl;
        const float w0 = W_fc[u], w1 = W_fc[H + u];
#pragma unroll
        for (int nt = 0; nt < 2; ++nt) {
            const __half2 hv = h2loc[nt * 2 + rr];
            const float h0 = __low2float(hv), h1 = __high2float(hv);
            acc[nt][0][0] = fmaf(h0, w0, acc[nt][0][0]);
            acc[nt][0][1] = fmaf(h0, w1, acc[nt][0][1]);
            acc[nt][1][0] = fmaf(h1, w0, acc[nt][1][0]);
            acc[nt][1][1] = fmaf(h1, w1, acc[nt][1][1]);
        }
    }
#pragma unroll
    for (int off = 4; off <= 16; off <<= 1)
#pragma unroll
        for (int nt = 0; nt < 2; ++nt)
#pragma unroll
            for (int e = 0; e < 2; ++e) {
                acc[nt][e][0] += __shfl_xor_sync(0xffffffffu, acc[nt][e][0], off);
                acc[nt][e][1] += __shfl_xor_sync(0xffffffffu, acc[nt][e][1], off);
            }
    float* scratch = (float*)(smraw + OFF_SCR + pair * 256);
    if (par == 1 && lane < 4) {
#pragma unroll
        for (int nt = 0; nt < 2; ++nt)
#pragma unroll
            for (int e = 0; e < 2; ++e) {
                const int col = nt * 8 + 2 * lane + e;
                scratch[col * 2 + 0] = acc[nt][e][0];
                scratch[col * 2 + 1] = acc[nt][e][1];
            }
    }
    BARP(barid);
    if (par == 0 && lane < 4) {
        const float f0 = b_fc[0], f1 = b_fc[1];
#pragma unroll
        for (int nt = 0; nt < 2; ++nt)
#pragma unroll
            for (int e = 0; e < 2; ++e) {
                const int col = nt * 8 + 2 * lane + e;
                out[(wb0 + col) * 2 + 0] = acc[nt][e][0] + scratch[col * 2 + 0] + f0;
                out[(wb0 + col) * 2 + 1] = acc[nt][e][1] + scratch[col * 2 + 1] + f1;
            }
    }
}

extern "C" void kernel_launch(void* const* d_in, const int* in_sizes, int n_in,
                              void* d_out, int out_size) {
    const float* x    = (const float*)d_in[0];
    const float* W_ih = (const float*)d_in[1];
    const float* W_hh = (const float*)d_in[2];
    const float* b_ih = (const float*)d_in[3];
    const float* b_hh = (const float*)d_in[4];
    const float* W_fc = (const float*)d_in[5];
    const float* b_fc = (const float*)d_in[6];
    float* out = (float*)d_out;

    int B = in_sizes[0] / (T_STEPS * NIN);
    int bpc = PAIRS * NB;                      // 64 batches per CTA
    int blocks = (B + bpc - 1) / bpc;
    lstm_msplit_kernel<<<blocks, THREADS>>>(x, W_ih, W_hh, b_ih, b_hh,
                                            W_fc, b_fc, out, B);
}